// round 1
// baseline (speedup 1.0000x reference)
#include <cuda_runtime.h>
#include <math.h>

#define B 64
#define T 512
#define E 768
#define H 72
#define BT (B*T)

// Scratch for projections (static device globals -- no allocation in kernel_launch)
__device__ float g_K[BT*H];
__device__ float g_Q[BT*H];
__device__ float g_V[BT*H];

// ---------------------------------------------------------------------------
// Projection GEMM: out[m][c] = sum_k x[m][k] * W[k][c]
// M = 32768, N = 72, K = 768. One blockIdx.y per weight matrix (K/Q/V).
// TILE_M = 128, TILE_K = 16, 256 threads, micro-tile 4 rows x 9 cols.
// ---------------------------------------------------------------------------
#define PTM 128
#define PTK 16

__global__ __launch_bounds__(256) void proj_kernel(
    const float* __restrict__ x,
    const float* __restrict__ Wk,
    const float* __restrict__ Wq,
    const float* __restrict__ Wv)
{
    const int which = blockIdx.y;
    const float* __restrict__ W   = (which == 0) ? Wk : ((which == 1) ? Wq : Wv);
    float* __restrict__ out       = (which == 0) ? g_K : ((which == 1) ? g_Q : g_V);
    const int m0 = blockIdx.x * PTM;

    __shared__ float Xs[PTK][PTM + 4];   // [k][m], padded for bank spread
    __shared__ float Ws[PTK][H];         // [k][c]

    const int t   = threadIdx.x;
    const int cxp = t & 7;     // col group: cols cxp*9 .. cxp*9+8
    const int ryp = t >> 3;    // row group: rows ryp*4 .. ryp*4+3

    float acc[4][9];
    #pragma unroll
    for (int i = 0; i < 4; i++)
        #pragma unroll
        for (int j = 0; j < 9; j++) acc[i][j] = 0.f;

    for (int k0 = 0; k0 < E; k0 += PTK) {
        // Load X tile [128 rows][16 k], stored transposed Xs[k][m]
        for (int i = t; i < PTM * PTK; i += 256) {
            int m = i >> 4, kk = i & 15;
            Xs[kk][m] = x[(size_t)(m0 + m) * E + k0 + kk];
        }
        // Load W tile [16 k][72 c]
        for (int i = t; i < PTK * H; i += 256) {
            int kk = i / H, c = i - kk * H;
            Ws[kk][c] = W[(size_t)(k0 + kk) * H + c];
        }
        __syncthreads();

        #pragma unroll
        for (int kk = 0; kk < PTK; kk++) {
            float4 a4 = *reinterpret_cast<const float4*>(&Xs[kk][ryp * 4]);
            float av0 = a4.x, av1 = a4.y, av2 = a4.z, av3 = a4.w;
            #pragma unroll
            for (int j = 0; j < 9; j++) {
                float bv = Ws[kk][cxp * 9 + j];
                acc[0][j] += av0 * bv;
                acc[1][j] += av1 * bv;
                acc[2][j] += av2 * bv;
                acc[3][j] += av3 * bv;
            }
        }
        __syncthreads();
    }

    #pragma unroll
    for (int i = 0; i < 4; i++)
        #pragma unroll
        for (int j = 0; j < 9; j++)
            out[(size_t)(m0 + ryp * 4 + i) * H + cxp * 9 + j] = acc[i][j];
}

// ---------------------------------------------------------------------------
// Flash attention: one block per (query-tile of 64 rows, batch).
// Online softmax. 256 threads.
//   S phase:  thread layout 16x16 (cx cols x4, ry rows x4)
//   PV phase: warp w -> rows w*8..w*8+7; lane: rl=lane>>3 (2 rows), cg=lane&7 (9 cols)
// ---------------------------------------------------------------------------
#define BR 64
#define BC 64
#define QK_PAD 68   // stride for [H][BR] transposed tiles (16B-aligned, bank-spread)
#define P_PAD  68

#define ATTN_SMEM_FLOATS (H*QK_PAD*2 + BC*H + BR*P_PAD + 3*BR)

__global__ __launch_bounds__(256) void attn_kernel(float* __restrict__ out)
{
    extern __shared__ float sm[];
    float* Qs   = sm;                      // [H][QK_PAD]  (transposed: [h][row])
    float* Ks   = Qs + H * QK_PAD;         // [H][QK_PAD]
    float* Vs   = Ks + H * QK_PAD;         // [BC][H]
    float* Ps   = Vs + BC * H;             // [BR][P_PAD]
    float* m_s  = Ps + BR * P_PAD;         // [BR] running max
    float* l_s  = m_s + BR;                // [BR] running denom
    float* sc_s = l_s + BR;                // [BR] rescale factor this tile

    const int qt = blockIdx.x;
    const int b  = blockIdx.y;
    const int t  = threadIdx.x;

    // S-phase mapping
    const int cx = t & 15;
    const int ry = t >> 4;
    // PV-phase mapping
    const int w    = t >> 5;
    const int lane = t & 31;
    const int r0   = w * 8 + (lane >> 3) * 2;   // rows r0, r0+1
    const int c0   = (lane & 7) * 9;            // cols c0..c0+8

    if (t < BR) { m_s[t] = -1e30f; l_s[t] = 0.f; }

    // Load Q tile, transposed into [h][row]
    const float* qsrc = g_Q + ((size_t)b * T + qt * BR) * H;
    for (int i = t; i < BR * H; i += 256) {
        int r = i / H, h = i - r * H;
        Qs[h * QK_PAD + r] = qsrc[i];
    }

    float o0[9], o1[9];
    #pragma unroll
    for (int j = 0; j < 9; j++) { o0[j] = 0.f; o1[j] = 0.f; }

    __syncthreads();

    const float scale = rsqrtf((float)H);

    for (int kt = 0; kt <= qt; kt++) {
        // Load K (transposed) and V tiles
        const float* ksrc = g_K + ((size_t)b * T + kt * BC) * H;
        const float* vsrc = g_V + ((size_t)b * T + kt * BC) * H;
        for (int i = t; i < BC * H; i += 256) {
            int r = i / H, h = i - r * H;
            Ks[h * QK_PAD + r] = ksrc[i];
            Vs[i] = vsrc[i];
        }
        __syncthreads();

        // ----- S = Q K^T (64x64, inner dim 72) -----
        float s[4][4];
        #pragma unroll
        for (int i = 0; i < 4; i++)
            #pragma unroll
            for (int j = 0; j < 4; j++) s[i][j] = 0.f;

        #pragma unroll 8
        for (int h = 0; h < H; h++) {
            float4 a = *reinterpret_cast<const float4*>(&Qs[h * QK_PAD + ry * 4]);
            float4 bb = *reinterpret_cast<const float4*>(&Ks[h * QK_PAD + cx * 4]);
            s[0][0] += a.x * bb.x; s[0][1] += a.x * bb.y; s[0][2] += a.x * bb.z; s[0][3] += a.x * bb.w;
            s[1][0] += a.y * bb.x; s[1][1] += a.y * bb.y; s[1][2] += a.y * bb.z; s[1][3] += a.y * bb.w;
            s[2][0] += a.z * bb.x; s[2][1] += a.z * bb.y; s[2][2] += a.z * bb.z; s[2][3] += a.z * bb.w;
            s[3][0] += a.w * bb.x; s[3][1] += a.w * bb.y; s[3][2] += a.w * bb.z; s[3][3] += a.w * bb.w;
        }

        const bool diag = (kt == qt);
        #pragma unroll
        for (int i = 0; i < 4; i++) {
            #pragma unroll
            for (int j = 0; j < 4; j++) {
                s[i][j] *= scale;
                if (diag && (cx * 4 + j) > (ry * 4 + i)) s[i][j] = -1e30f;
            }
        }

        // ----- online softmax over the 64 cols (across 16 cx lanes) -----
        const int lr = ry * 4;
        float mn[4], sc[4], rs[4];
        #pragma unroll
        for (int i = 0; i < 4; i++) {
            float rm = fmaxf(fmaxf(s[i][0], s[i][1]), fmaxf(s[i][2], s[i][3]));
            #pragma unroll
            for (int off = 1; off < 16; off <<= 1)
                rm = fmaxf(rm, __shfl_xor_sync(0xffffffffu, rm, off));
            float mo = m_s[lr + i];
            mn[i] = fmaxf(mo, rm);
            sc[i] = __expf(mo - mn[i]);
            float p0v = __expf(s[i][0] - mn[i]);
            float p1v = __expf(s[i][1] - mn[i]);
            float p2v = __expf(s[i][2] - mn[i]);
            float p3v = __expf(s[i][3] - mn[i]);
            rs[i] = p0v + p1v + p2v + p3v;
            *reinterpret_cast<float4*>(&Ps[(lr + i) * P_PAD + cx * 4]) =
                make_float4(p0v, p1v, p2v, p3v);
            #pragma unroll
            for (int off = 1; off < 16; off <<= 1)
                rs[i] += __shfl_xor_sync(0xffffffffu, rs[i], off);
        }
        if (cx == 0) {
            #pragma unroll
            for (int i = 0; i < 4; i++) {
                m_s[lr + i]  = mn[i];
                l_s[lr + i]  = l_s[lr + i] * sc[i] + rs[i];
                sc_s[lr + i] = sc[i];
            }
        }
        __syncthreads();

        // ----- O = O*scale + P V -----
        {
            float sA = sc_s[r0];
            float sB = sc_s[r0 + 1];
            #pragma unroll
            for (int j = 0; j < 9; j++) { o0[j] *= sA; o1[j] *= sB; }
        }
        #pragma unroll 4
        for (int j = 0; j < BC; j++) {
            float p0 = Ps[r0 * P_PAD + j];
            float p1 = Ps[(r0 + 1) * P_PAD + j];
            const float* vrow = &Vs[j * H + c0];
            #pragma unroll
            for (int c = 0; c < 9; c++) {
                float v = vrow[c];
                o0[c] += p0 * v;
                o1[c] += p1 * v;
            }
        }
        __syncthreads();
    }

    // Epilogue: divide by denominator, write out [B,T,H]
    float inv0 = 1.f / l_s[r0];
    float inv1 = 1.f / l_s[r0 + 1];
    float* od = out + ((size_t)b * T + qt * BR) * H;
    #pragma unroll
    for (int c = 0; c < 9; c++) {
        od[(size_t)r0 * H + c0 + c]       = o0[c] * inv0;
        od[(size_t)(r0 + 1) * H + c0 + c] = o1[c] * inv1;
    }
}

// ---------------------------------------------------------------------------
extern "C" void kernel_launch(void* const* d_in, const int* in_sizes, int n_in,
                              void* d_out, int out_size)
{
    const float* x  = (const float*)d_in[0];
    const float* Wk = (const float*)d_in[1];
    const float* Wq = (const float*)d_in[2];
    const float* Wv = (const float*)d_in[3];
    float* out = (float*)d_out;

    dim3 pg(BT / PTM, 3);
    proj_kernel<<<pg, 256>>>(x, Wk, Wq, Wv);

    int smem = ATTN_SMEM_FLOATS * (int)sizeof(float);
    cudaFuncSetAttribute(attn_kernel, cudaFuncAttributeMaxDynamicSharedMemorySize, smem);
    attn_kernel<<<dim3(T / BR, B), 256, smem>>>(out);
}

// round 2
// speedup vs baseline: 1.5092x; 1.5092x over previous
#include <cuda_runtime.h>
#include <cuda_bf16.h>
#include <math.h>

#define B 64
#define T 512
#define E 768
#define H 72
#define BT (B*T)

// Scratch for projections (static device globals -- no allocation in kernel_launch)
__device__ float g_K[BT*H];
__device__ float g_Q[BT*H];
__device__ float g_V[BT*H];

// ---------------------------------------------------------------------------
// Projection GEMM via split-bf16 tensor-core mma:
//   out[m][c] = sum_k x[m][k] * W[k][c],  M=32768, N=72, K=768
// x split on the fly into hi/lo bf16; 3-term mma (hi*hi + hi*lo + lo*hi),
// fp32 accumulation -> ~1e-5 relative error.
// CTA: 256 threads (8 warps), M-tile 128 (16 rows/warp), all 9 n8 tiles,
// K chunked at CK=64 with W staged hi/lo in smem as [n][k].
// ---------------------------------------------------------------------------
#define CK 66   // padded k stride for W smem (64 real + 2 pad)

__device__ __forceinline__ void mma16816(float* c, const unsigned* a, const unsigned* b)
{
    asm volatile(
        "mma.sync.aligned.m16n8k16.row.col.f32.bf16.bf16.f32 "
        "{%0,%1,%2,%3}, {%4,%5,%6,%7}, {%8,%9}, {%0,%1,%2,%3};\n"
        : "+f"(c[0]), "+f"(c[1]), "+f"(c[2]), "+f"(c[3])
        : "r"(a[0]), "r"(a[1]), "r"(a[2]), "r"(a[3]), "r"(b[0]), "r"(b[1]));
}

// split a float2 into packed bf16x2 hi and lo words
__device__ __forceinline__ void split2(float2 v, unsigned& hi, unsigned& lo)
{
    __nv_bfloat16 h0 = __float2bfloat16(v.x);
    __nv_bfloat16 h1 = __float2bfloat16(v.y);
    __nv_bfloat16 l0 = __float2bfloat16(v.x - __bfloat162float(h0));
    __nv_bfloat16 l1 = __float2bfloat16(v.y - __bfloat162float(h1));
    __nv_bfloat162 hp = __halves2bfloat162(h0, h1);
    __nv_bfloat162 lp = __halves2bfloat162(l0, l1);
    hi = *reinterpret_cast<unsigned*>(&hp);
    lo = *reinterpret_cast<unsigned*>(&lp);
}

__global__ __launch_bounds__(256) void proj_kernel(
    const float* __restrict__ x,
    const float* __restrict__ Wk,
    const float* __restrict__ Wq,
    const float* __restrict__ Wv)
{
    const int which = blockIdx.y;
    const float* __restrict__ W = (which == 0) ? Wk : ((which == 1) ? Wq : Wv);
    float* __restrict__ out     = (which == 0) ? g_K : ((which == 1) ? g_Q : g_V);

    __shared__ __nv_bfloat16 Wt_hi[H * CK];   // [n][k] packed, k local 0..63
    __shared__ __nv_bfloat16 Wt_lo[H * CK];

    const int t    = threadIdx.x;
    const int wid  = t >> 5;
    const int lane = t & 31;
    const int g    = lane >> 2;        // group id (row within m16 / n within n8)
    const int c2   = (lane & 3) * 2;   // k-pair offset

    const int m0 = blockIdx.x * 128 + wid * 16;
    const size_t rowA = (size_t)(m0 + g) * E;      // row g
    const size_t rowB = (size_t)(m0 + g + 8) * E;  // row g+8

    float acc[9][4];
    #pragma unroll
    for (int nt = 0; nt < 9; nt++)
        #pragma unroll
        for (int i = 0; i < 4; i++) acc[nt][i] = 0.f;

    for (int kc = 0; kc < E; kc += 64) {
        __syncthreads();   // protect smem from previous chunk's readers
        // stage W chunk [64 k][72 n] -> smem [n][k] hi/lo
        for (int i = t; i < 64 * H; i += 256) {
            int kk = i / H, n = i - kk * H;
            float w = W[(size_t)(kc + kk) * H + n];
            __nv_bfloat16 h = __float2bfloat16(w);
            __nv_bfloat16 l = __float2bfloat16(w - __bfloat162float(h));
            Wt_hi[n * CK + kk] = h;
            Wt_lo[n * CK + kk] = l;
        }
        __syncthreads();

        #pragma unroll
        for (int s = 0; s < 4; s++) {
            const int k = kc + s * 16;
            // ---- A fragments: load fp32, split hi/lo on the fly ----
            float2 v0 = *reinterpret_cast<const float2*>(&x[rowA + k + c2]);
            float2 v1 = *reinterpret_cast<const float2*>(&x[rowB + k + c2]);
            float2 v2 = *reinterpret_cast<const float2*>(&x[rowA + k + 8 + c2]);
            float2 v3 = *reinterpret_cast<const float2*>(&x[rowB + k + 8 + c2]);
            unsigned ahi[4], alo[4];
            split2(v0, ahi[0], alo[0]);
            split2(v1, ahi[1], alo[1]);
            split2(v2, ahi[2], alo[2]);
            split2(v3, ahi[3], alo[3]);

            const int kb = s * 16 + c2;   // local k offset for B frag
            #pragma unroll
            for (int nt = 0; nt < 9; nt++) {
                const int nrow = nt * 8 + g;
                unsigned bhi[2], blo[2];
                bhi[0] = *reinterpret_cast<const unsigned*>(&Wt_hi[nrow * CK + kb]);
                bhi[1] = *reinterpret_cast<const unsigned*>(&Wt_hi[nrow * CK + kb + 8]);
                blo[0] = *reinterpret_cast<const unsigned*>(&Wt_lo[nrow * CK + kb]);
                blo[1] = *reinterpret_cast<const unsigned*>(&Wt_lo[nrow * CK + kb + 8]);
                mma16816(acc[nt], ahi, bhi);
                mma16816(acc[nt], ahi, blo);
                mma16816(acc[nt], alo, bhi);
            }
        }
    }

    // epilogue: C frag -> out. rows m0+g, m0+g+8; cols nt*8 + c2, +1
    #pragma unroll
    for (int nt = 0; nt < 9; nt++) {
        const int col = nt * 8 + c2;
        *reinterpret_cast<float2*>(&out[(size_t)(m0 + g) * H + col]) =
            make_float2(acc[nt][0], acc[nt][1]);
        *reinterpret_cast<float2*>(&out[(size_t)(m0 + g + 8) * H + col]) =
            make_float2(acc[nt][2], acc[nt][3]);
    }
}

// ---------------------------------------------------------------------------
// Flash attention: one block per (query-tile of 64 rows, batch).
// Online softmax. 256 threads. (unchanged from round 1)
// ---------------------------------------------------------------------------
#define BR 64
#define BC 64
#define QK_PAD 68
#define P_PAD  68

#define ATTN_SMEM_FLOATS (H*QK_PAD*2 + BC*H + BR*P_PAD + 3*BR)

__global__ __launch_bounds__(256) void attn_kernel(float* __restrict__ out)
{
    extern __shared__ float sm[];
    float* Qs   = sm;                      // [H][QK_PAD]  (transposed: [h][row])
    float* Ks   = Qs + H * QK_PAD;         // [H][QK_PAD]
    float* Vs   = Ks + H * QK_PAD;         // [BC][H]
    float* Ps   = Vs + BC * H;             // [BR][P_PAD]
    float* m_s  = Ps + BR * P_PAD;         // [BR] running max
    float* l_s  = m_s + BR;                // [BR] running denom
    float* sc_s = l_s + BR;                // [BR] rescale factor this tile

    const int qt = blockIdx.x;
    const int b  = blockIdx.y;
    const int t  = threadIdx.x;

    const int cx = t & 15;
    const int ry = t >> 4;
    const int w    = t >> 5;
    const int lane = t & 31;
    const int r0   = w * 8 + (lane >> 3) * 2;
    const int c0   = (lane & 7) * 9;

    if (t < BR) { m_s[t] = -1e30f; l_s[t] = 0.f; }

    const float* qsrc = g_Q + ((size_t)b * T + qt * BR) * H;
    for (int i = t; i < BR * H; i += 256) {
        int r = i / H, h = i - r * H;
        Qs[h * QK_PAD + r] = qsrc[i];
    }

    float o0[9], o1[9];
    #pragma unroll
    for (int j = 0; j < 9; j++) { o0[j] = 0.f; o1[j] = 0.f; }

    __syncthreads();

    const float scale = rsqrtf((float)H);

    for (int kt = 0; kt <= qt; kt++) {
        const float* ksrc = g_K + ((size_t)b * T + kt * BC) * H;
        const float* vsrc = g_V + ((size_t)b * T + kt * BC) * H;
        for (int i = t; i < BC * H; i += 256) {
            int r = i / H, h = i - r * H;
            Ks[h * QK_PAD + r] = ksrc[i];
            Vs[i] = vsrc[i];
        }
        __syncthreads();

        float s[4][4];
        #pragma unroll
        for (int i = 0; i < 4; i++)
            #pragma unroll
            for (int j = 0; j < 4; j++) s[i][j] = 0.f;

        #pragma unroll 8
        for (int h = 0; h < H; h++) {
            float4 a = *reinterpret_cast<const float4*>(&Qs[h * QK_PAD + ry * 4]);
            float4 bb = *reinterpret_cast<const float4*>(&Ks[h * QK_PAD + cx * 4]);
            s[0][0] += a.x * bb.x; s[0][1] += a.x * bb.y; s[0][2] += a.x * bb.z; s[0][3] += a.x * bb.w;
            s[1][0] += a.y * bb.x; s[1][1] += a.y * bb.y; s[1][2] += a.y * bb.z; s[1][3] += a.y * bb.w;
            s[2][0] += a.z * bb.x; s[2][1] += a.z * bb.y; s[2][2] += a.z * bb.z; s[2][3] += a.z * bb.w;
            s[3][0] += a.w * bb.x; s[3][1] += a.w * bb.y; s[3][2] += a.w * bb.z; s[3][3] += a.w * bb.w;
        }

        const bool diag = (kt == qt);
        #pragma unroll
        for (int i = 0; i < 4; i++) {
            #pragma unroll
            for (int j = 0; j < 4; j++) {
                s[i][j] *= scale;
                if (diag && (cx * 4 + j) > (ry * 4 + i)) s[i][j] = -1e30f;
            }
        }

        const int lr = ry * 4;
        float mn[4], sc[4], rs[4];
        #pragma unroll
        for (int i = 0; i < 4; i++) {
            float rm = fmaxf(fmaxf(s[i][0], s[i][1]), fmaxf(s[i][2], s[i][3]));
            #pragma unroll
            for (int off = 1; off < 16; off <<= 1)
                rm = fmaxf(rm, __shfl_xor_sync(0xffffffffu, rm, off));
            float mo = m_s[lr + i];
            mn[i] = fmaxf(mo, rm);
            sc[i] = __expf(mo - mn[i]);
            float p0v = __expf(s[i][0] - mn[i]);
            float p1v = __expf(s[i][1] - mn[i]);
            float p2v = __expf(s[i][2] - mn[i]);
            float p3v = __expf(s[i][3] - mn[i]);
            rs[i] = p0v + p1v + p2v + p3v;
            *reinterpret_cast<float4*>(&Ps[(lr + i) * P_PAD + cx * 4]) =
                make_float4(p0v, p1v, p2v, p3v);
            #pragma unroll
            for (int off = 1; off < 16; off <<= 1)
                rs[i] += __shfl_xor_sync(0xffffffffu, rs[i], off);
        }
        if (cx == 0) {
            #pragma unroll
            for (int i = 0; i < 4; i++) {
                m_s[lr + i]  = mn[i];
                l_s[lr + i]  = l_s[lr + i] * sc[i] + rs[i];
                sc_s[lr + i] = sc[i];
            }
        }
        __syncthreads();

        {
            float sA = sc_s[r0];
            float sB = sc_s[r0 + 1];
            #pragma unroll
            for (int j = 0; j < 9; j++) { o0[j] *= sA; o1[j] *= sB; }
        }
        #pragma unroll 4
        for (int j = 0; j < BC; j++) {
            float p0 = Ps[r0 * P_PAD + j];
            float p1 = Ps[(r0 + 1) * P_PAD + j];
            const float* vrow = &Vs[j * H + c0];
            #pragma unroll
            for (int c = 0; c < 9; c++) {
                float v = vrow[c];
                o0[c] += p0 * v;
                o1[c] += p1 * v;
            }
        }
        __syncthreads();
    }

    float inv0 = 1.f / l_s[r0];
    float inv1 = 1.f / l_s[r0 + 1];
    float* od = out + ((size_t)b * T + qt * BR) * H;
    #pragma unroll
    for (int c = 0; c < 9; c++) {
        od[(size_t)r0 * H + c0 + c]       = o0[c] * inv0;
        od[(size_t)(r0 + 1) * H + c0 + c] = o1[c] * inv1;
    }
}

// ---------------------------------------------------------------------------
extern "C" void kernel_launch(void* const* d_in, const int* in_sizes, int n_in,
                              void* d_out, int out_size)
{
    const float* x  = (const float*)d_in[0];
    const float* Wk = (const float*)d_in[1];
    const float* Wq = (const float*)d_in[2];
    const float* Wv = (const float*)d_in[3];
    float* out = (float*)d_out;

    dim3 pg(BT / 128, 3);
    proj_kernel<<<pg, 256>>>(x, Wk, Wq, Wv);

    int smem = ATTN_SMEM_FLOATS * (int)sizeof(float);
    cudaFuncSetAttribute(attn_kernel, cudaFuncAttributeMaxDynamicSharedMemorySize, smem);
    attn_kernel<<<dim3(T / BR, B), 256, smem>>>(out);
}

// round 3
// speedup vs baseline: 2.1543x; 1.4274x over previous
#include <cuda_runtime.h>
#include <cuda_bf16.h>
#include <math.h>

#define B 64
#define T 512
#define E 768
#define H 72
#define BT (B*T)

#define NS   48              // k16 steps over K=768
#define NG   216             // total output cols (3*72)
#define WPIDX (NG*NS*4)      // uint4 count in packed W

// Scratch (static device globals -- no allocation in kernel_launch)
__device__ float g_K[BT*H];
__device__ float g_Q[BT*H];
__device__ float g_V[BT*H];
// Packed W: index ((n_global*48 + s)*4 + c2g), one uint4 =
//   {hi(k,k+1), hi(k+8,k+9), lo(k,k+1), lo(k+8,k+9)},  k = s*16 + c2g*2
__device__ uint4 g_Wp[WPIDX];

__device__ __forceinline__ void mma16816(float* c, const unsigned* a, const unsigned* b)
{
    asm volatile(
        "mma.sync.aligned.m16n8k16.row.col.f32.bf16.bf16.f32 "
        "{%0,%1,%2,%3}, {%4,%5,%6,%7}, {%8,%9}, {%0,%1,%2,%3};\n"
        : "+f"(c[0]), "+f"(c[1]), "+f"(c[2]), "+f"(c[3])
        : "r"(a[0]), "r"(a[1]), "r"(a[2]), "r"(a[3]), "r"(b[0]), "r"(b[1]));
}

__device__ __forceinline__ unsigned pack_hi2(float a, float b)
{
    __nv_bfloat162 p = __halves2bfloat162(__float2bfloat16(a), __float2bfloat16(b));
    return *reinterpret_cast<unsigned*>(&p);
}
__device__ __forceinline__ unsigned pack_lo2(float a, float b)
{
    __nv_bfloat16 ha = __float2bfloat16(a);
    __nv_bfloat16 hb = __float2bfloat16(b);
    __nv_bfloat162 p = __halves2bfloat162(
        __float2bfloat16(a - __bfloat162float(ha)),
        __float2bfloat16(b - __bfloat162float(hb)));
    return *reinterpret_cast<unsigned*>(&p);
}
__device__ __forceinline__ void split2(float2 v, unsigned& hi, unsigned& lo)
{
    hi = pack_hi2(v.x, v.y);
    lo = pack_lo2(v.x, v.y);
}

// ---------------------------------------------------------------------------
// prep_w: pack Wk|Wq|Wv into mma B-fragment layout (global, L2-resident)
// ---------------------------------------------------------------------------
__global__ __launch_bounds__(256) void prep_w(
    const float* __restrict__ Wk,
    const float* __restrict__ Wq,
    const float* __restrict__ Wv)
{
    int idx = blockIdx.x * 256 + threadIdx.x;
    if (idx >= WPIDX) return;
    int c2g = idx & 3;
    int s   = (idx >> 2) % NS;
    int ng  = idx / (4 * NS);          // 0..215
    int which = ng / H;
    int n     = ng - which * H;
    const float* __restrict__ W = (which == 0) ? Wk : ((which == 1) ? Wq : Wv);
    int k = s * 16 + c2g * 2;
    float w00 = W[(size_t)(k + 0) * H + n];
    float w01 = W[(size_t)(k + 1) * H + n];
    float w10 = W[(size_t)(k + 8) * H + n];
    float w11 = W[(size_t)(k + 9) * H + n];
    uint4 p;
    p.x = pack_hi2(w00, w01);
    p.y = pack_hi2(w10, w11);
    p.z = pack_lo2(w00, w01);
    p.w = pack_lo2(w10, w11);
    g_Wp[idx] = p;
}

// ---------------------------------------------------------------------------
// Fused projection GEMM: K,Q,V in one pass.
//   M = 32768, Nfused = 216, K = 768. split-bf16 3-term mma, fp32 accum.
// 256 threads (8 warps), M-tile 128 (16 rows/warp), 27 n8-tiles per warp.
// No smem, no barriers: B-frags via LDG.128 from packed W (L1/L2-resident),
// A prefetched one k16-step ahead.
// ---------------------------------------------------------------------------
__global__ __launch_bounds__(256) void proj_kernel(const float* __restrict__ x)
{
    const int t    = threadIdx.x;
    const int wid  = t >> 5;
    const int lane = t & 31;
    const int g    = lane >> 2;        // row/col group within fragment
    const int c2   = (lane & 3) * 2;   // k-pair offset
    const int c2g  = lane & 3;

    const int m0 = blockIdx.x * 128 + wid * 16;
    const float* __restrict__ pA = x + (size_t)(m0 + g) * E;
    const float* __restrict__ pB = x + (size_t)(m0 + g + 8) * E;

    float acc[27][4];
    #pragma unroll
    for (int nt = 0; nt < 27; nt++)
        #pragma unroll
        for (int i = 0; i < 4; i++) acc[nt][i] = 0.f;

    // B-frag base pointer for this lane (stride per nt = 8*48*4 uint4)
    const uint4* __restrict__ wbase = g_Wp + (size_t)(g * NS) * 4 + c2g;

    float2 cur[4];
    cur[0] = *reinterpret_cast<const float2*>(pA + c2);
    cur[1] = *reinterpret_cast<const float2*>(pB + c2);
    cur[2] = *reinterpret_cast<const float2*>(pA + 8 + c2);
    cur[3] = *reinterpret_cast<const float2*>(pB + 8 + c2);

    for (int s = 0; s < NS; s++) {
        float2 nxt[4];
        if (s < NS - 1) {
            const int k = (s + 1) * 16;
            nxt[0] = *reinterpret_cast<const float2*>(pA + k + c2);
            nxt[1] = *reinterpret_cast<const float2*>(pB + k + c2);
            nxt[2] = *reinterpret_cast<const float2*>(pA + k + 8 + c2);
            nxt[3] = *reinterpret_cast<const float2*>(pB + k + 8 + c2);
        }

        unsigned ahi[4], alo[4];
        split2(cur[0], ahi[0], alo[0]);
        split2(cur[1], ahi[1], alo[1]);
        split2(cur[2], ahi[2], alo[2]);
        split2(cur[3], ahi[3], alo[3]);

        const uint4* __restrict__ wp = wbase + s * 4;
        #pragma unroll
        for (int nt = 0; nt < 27; nt++) {
            uint4 bw = __ldg(wp + (size_t)nt * (8 * NS * 4));
            unsigned bhi[2] = { bw.x, bw.y };
            unsigned blo[2] = { bw.z, bw.w };
            mma16816(acc[nt], ahi, bhi);
            mma16816(acc[nt], ahi, blo);
            mma16816(acc[nt], alo, bhi);
        }

        cur[0] = nxt[0]; cur[1] = nxt[1]; cur[2] = nxt[2]; cur[3] = nxt[3];
    }

    // epilogue: nt -> (which, col-block). rows m0+g, m0+g+8; cols (nt%9)*8+c2
    #pragma unroll
    for (int nt = 0; nt < 27; nt++) {
        const int which = nt / 9;
        float* __restrict__ out = (which == 0) ? g_K : ((which == 1) ? g_Q : g_V);
        const int col = (nt - which * 9) * 8 + c2;
        *reinterpret_cast<float2*>(&out[(size_t)(m0 + g) * H + col]) =
            make_float2(acc[nt][0], acc[nt][1]);
        *reinterpret_cast<float2*>(&out[(size_t)(m0 + g + 8) * H + col]) =
            make_float2(acc[nt][2], acc[nt][3]);
    }
}

// ---------------------------------------------------------------------------
// Flash attention (unchanged from round 1/2)
// ---------------------------------------------------------------------------
#define BR 64
#define BC 64
#define QK_PAD 68
#define P_PAD  68

#define ATTN_SMEM_FLOATS (H*QK_PAD*2 + BC*H + BR*P_PAD + 3*BR)

__global__ __launch_bounds__(256) void attn_kernel(float* __restrict__ out)
{
    extern __shared__ float sm[];
    float* Qs   = sm;
    float* Ks   = Qs + H * QK_PAD;
    float* Vs   = Ks + H * QK_PAD;
    float* Ps   = Vs + BC * H;
    float* m_s  = Ps + BR * P_PAD;
    float* l_s  = m_s + BR;
    float* sc_s = l_s + BR;

    const int qt = blockIdx.x;
    const int b  = blockIdx.y;
    const int t  = threadIdx.x;

    const int cx = t & 15;
    const int ry = t >> 4;
    const int w    = t >> 5;
    const int lane = t & 31;
    const int r0   = w * 8 + (lane >> 3) * 2;
    const int c0   = (lane & 7) * 9;

    if (t < BR) { m_s[t] = -1e30f; l_s[t] = 0.f; }

    const float* qsrc = g_Q + ((size_t)b * T + qt * BR) * H;
    for (int i = t; i < BR * H; i += 256) {
        int r = i / H, h = i - r * H;
        Qs[h * QK_PAD + r] = qsrc[i];
    }

    float o0[9], o1[9];
    #pragma unroll
    for (int j = 0; j < 9; j++) { o0[j] = 0.f; o1[j] = 0.f; }

    __syncthreads();

    const float scale = rsqrtf((float)H);

    for (int kt = 0; kt <= qt; kt++) {
        const float* ksrc = g_K + ((size_t)b * T + kt * BC) * H;
        const float* vsrc = g_V + ((size_t)b * T + kt * BC) * H;
        for (int i = t; i < BC * H; i += 256) {
            int r = i / H, h = i - r * H;
            Ks[h * QK_PAD + r] = ksrc[i];
            Vs[i] = vsrc[i];
        }
        __syncthreads();

        float s[4][4];
        #pragma unroll
        for (int i = 0; i < 4; i++)
            #pragma unroll
            for (int j = 0; j < 4; j++) s[i][j] = 0.f;

        #pragma unroll 8
        for (int h = 0; h < H; h++) {
            float4 a = *reinterpret_cast<const float4*>(&Qs[h * QK_PAD + ry * 4]);
            float4 bb = *reinterpret_cast<const float4*>(&Ks[h * QK_PAD + cx * 4]);
            s[0][0] += a.x * bb.x; s[0][1] += a.x * bb.y; s[0][2] += a.x * bb.z; s[0][3] += a.x * bb.w;
            s[1][0] += a.y * bb.x; s[1][1] += a.y * bb.y; s[1][2] += a.y * bb.z; s[1][3] += a.y * bb.w;
            s[2][0] += a.z * bb.x; s[2][1] += a.z * bb.y; s[2][2] += a.z * bb.z; s[2][3] += a.z * bb.w;
            s[3][0] += a.w * bb.x; s[3][1] += a.w * bb.y; s[3][2] += a.w * bb.z; s[3][3] += a.w * bb.w;
        }

        const bool diag = (kt == qt);
        #pragma unroll
        for (int i = 0; i < 4; i++) {
            #pragma unroll
            for (int j = 0; j < 4; j++) {
                s[i][j] *= scale;
                if (diag && (cx * 4 + j) > (ry * 4 + i)) s[i][j] = -1e30f;
            }
        }

        const int lr = ry * 4;
        float mn[4], sc[4], rs[4];
        #pragma unroll
        for (int i = 0; i < 4; i++) {
            float rm = fmaxf(fmaxf(s[i][0], s[i][1]), fmaxf(s[i][2], s[i][3]));
            #pragma unroll
            for (int off = 1; off < 16; off <<= 1)
                rm = fmaxf(rm, __shfl_xor_sync(0xffffffffu, rm, off));
            float mo = m_s[lr + i];
            mn[i] = fmaxf(mo, rm);
            sc[i] = __expf(mo - mn[i]);
            float p0v = __expf(s[i][0] - mn[i]);
            float p1v = __expf(s[i][1] - mn[i]);
            float p2v = __expf(s[i][2] - mn[i]);
            float p3v = __expf(s[i][3] - mn[i]);
            rs[i] = p0v + p1v + p2v + p3v;
            *reinterpret_cast<float4*>(&Ps[(lr + i) * P_PAD + cx * 4]) =
                make_float4(p0v, p1v, p2v, p3v);
            #pragma unroll
            for (int off = 1; off < 16; off <<= 1)
                rs[i] += __shfl_xor_sync(0xffffffffu, rs[i], off);
        }
        if (cx == 0) {
            #pragma unroll
            for (int i = 0; i < 4; i++) {
                m_s[lr + i]  = mn[i];
                l_s[lr + i]  = l_s[lr + i] * sc[i] + rs[i];
                sc_s[lr + i] = sc[i];
            }
        }
        __syncthreads();

        {
            float sA = sc_s[r0];
            float sB = sc_s[r0 + 1];
            #pragma unroll
            for (int j = 0; j < 9; j++) { o0[j] *= sA; o1[j] *= sB; }
        }
        #pragma unroll 4
        for (int j = 0; j < BC; j++) {
            float p0 = Ps[r0 * P_PAD + j];
            float p1 = Ps[(r0 + 1) * P_PAD + j];
            const float* vrow = &Vs[j * H + c0];
            #pragma unroll
            for (int c = 0; c < 9; c++) {
                float v = vrow[c];
                o0[c] += p0 * v;
                o1[c] += p1 * v;
            }
        }
        __syncthreads();
    }

    float inv0 = 1.f / l_s[r0];
    float inv1 = 1.f / l_s[r0 + 1];
    float* od = out + ((size_t)b * T + qt * BR) * H;
    #pragma unroll
    for (int c = 0; c < 9; c++) {
        od[(size_t)r0 * H + c0 + c]       = o0[c] * inv0;
        od[(size_t)(r0 + 1) * H + c0 + c] = o1[c] * inv1;
    }
}

// ---------------------------------------------------------------------------
extern "C" void kernel_launch(void* const* d_in, const int* in_sizes, int n_in,
                              void* d_out, int out_size)
{
    const float* x  = (const float*)d_in[0];
    const float* Wk = (const float*)d_in[1];
    const float* Wq = (const float*)d_in[2];
    const float* Wv = (const float*)d_in[3];
    float* out = (float*)d_out;

    prep_w<<<(WPIDX + 255) / 256, 256>>>(Wk, Wq, Wv);
    proj_kernel<<<BT / 128, 256>>>(x);

    int smem = ATTN_SMEM_FLOATS * (int)sizeof(float);
    cudaFuncSetAttribute(attn_kernel, cudaFuncAttributeMaxDynamicSharedMemorySize, smem);
    attn_kernel<<<dim3(T / BR, B), 256, smem>>>(out);
}

// round 5
// speedup vs baseline: 2.2513x; 1.0450x over previous
#include <cuda_runtime.h>
#include <cuda_bf16.h>
#include <math.h>

#define B 64
#define T 512
#define E 768
#define H 72
#define BT (B*T)

#define NS   48              // k16 steps over K=768
#define NG   216             // total output cols (3*72)
#define WPIDX (NG*NS*4)      // uint4 count in packed W
#define HPAIR 36             // h-pairs per row for packed Q/K
#define TPAIR 256            // token-pairs per (b,n) row for packed V

#define QSCALE 0.11785113019775793f   // 1/sqrt(72)

// Scratch (static device globals -- no allocation in kernel_launch)
__device__ float g_V[BT*H];
__device__ unsigned g_Qp_hi[BT*HPAIR];
__device__ unsigned g_Qp_lo[BT*HPAIR];
__device__ unsigned g_Kp_hi[BT*HPAIR];
__device__ unsigned g_Kp_lo[BT*HPAIR];
__device__ unsigned g_Vp_hi[B*H*TPAIR];
__device__ unsigned g_Vp_lo[B*H*TPAIR];
__device__ uint4 g_Wp[WPIDX];

__device__ __forceinline__ void mma16816(float* c, const unsigned* a, const unsigned* b)
{
    asm volatile(
        "mma.sync.aligned.m16n8k16.row.col.f32.bf16.bf16.f32 "
        "{%0,%1,%2,%3}, {%4,%5,%6,%7}, {%8,%9}, {%0,%1,%2,%3};\n"
        : "+f"(c[0]), "+f"(c[1]), "+f"(c[2]), "+f"(c[3])
        : "r"(a[0]), "r"(a[1]), "r"(a[2]), "r"(a[3]), "r"(b[0]), "r"(b[1]));
}

__device__ __forceinline__ unsigned pack_hi2(float a, float b)
{
    __nv_bfloat162 p = __halves2bfloat162(__float2bfloat16(a), __float2bfloat16(b));
    return *reinterpret_cast<unsigned*>(&p);
}
__device__ __forceinline__ unsigned pack_lo2(float a, float b)
{
    __nv_bfloat16 ha = __float2bfloat16(a);
    __nv_bfloat16 hb = __float2bfloat16(b);
    __nv_bfloat162 p = __halves2bfloat162(
        __float2bfloat16(a - __bfloat162float(ha)),
        __float2bfloat16(b - __bfloat162float(hb)));
    return *reinterpret_cast<unsigned*>(&p);
}
__device__ __forceinline__ void split2(float2 v, unsigned& hi, unsigned& lo)
{
    hi = pack_hi2(v.x, v.y);
    lo = pack_lo2(v.x, v.y);
}

// ---------------------------------------------------------------------------
// prep_w: pack Wk|Wq|Wv into mma B-fragment layout (global, L2-resident)
// ---------------------------------------------------------------------------
__global__ __launch_bounds__(256) void prep_w(
    const float* __restrict__ Wk,
    const float* __restrict__ Wq,
    const float* __restrict__ Wv)
{
    int idx = blockIdx.x * 256 + threadIdx.x;
    if (idx >= WPIDX) return;
    int c2g = idx & 3;
    int s   = (idx >> 2) % NS;
    int ng  = idx / (4 * NS);
    int which = ng / H;
    int n     = ng - which * H;
    const float* __restrict__ W = (which == 0) ? Wk : ((which == 1) ? Wq : Wv);
    int k = s * 16 + c2g * 2;
    float w00 = W[(size_t)(k + 0) * H + n];
    float w01 = W[(size_t)(k + 1) * H + n];
    float w10 = W[(size_t)(k + 8) * H + n];
    float w11 = W[(size_t)(k + 9) * H + n];
    uint4 p;
    p.x = pack_hi2(w00, w01);
    p.y = pack_hi2(w10, w11);
    p.z = pack_lo2(w00, w01);
    p.w = pack_lo2(w10, w11);
    g_Wp[idx] = p;
}

// ---------------------------------------------------------------------------
// Fused projection GEMM (K,Q,V): emits K,Q packed hi/lo bf16x2 h-pairs
// (Q pre-scaled by 1/sqrt(H)), V as fp32.
// ---------------------------------------------------------------------------
__global__ __launch_bounds__(256) void proj_kernel(const float* __restrict__ x)
{
    const int t    = threadIdx.x;
    const int wid  = t >> 5;
    const int lane = t & 31;
    const int g    = lane >> 2;
    const int c2   = (lane & 3) * 2;
    const int c2g  = lane & 3;

    const int m0 = blockIdx.x * 128 + wid * 16;
    const float* __restrict__ pA = x + (size_t)(m0 + g) * E;
    const float* __restrict__ pB = x + (size_t)(m0 + g + 8) * E;

    float acc[27][4];
    #pragma unroll
    for (int nt = 0; nt < 27; nt++)
        #pragma unroll
        for (int i = 0; i < 4; i++) acc[nt][i] = 0.f;

    const uint4* __restrict__ wbase = g_Wp + (size_t)(g * NS) * 4 + c2g;

    float2 cur[4];
    cur[0] = *reinterpret_cast<const float2*>(pA + c2);
    cur[1] = *reinterpret_cast<const float2*>(pB + c2);
    cur[2] = *reinterpret_cast<const float2*>(pA + 8 + c2);
    cur[3] = *reinterpret_cast<const float2*>(pB + 8 + c2);

    for (int s = 0; s < NS; s++) {
        float2 nxt[4];
        if (s < NS - 1) {
            const int k = (s + 1) * 16;
            nxt[0] = *reinterpret_cast<const float2*>(pA + k + c2);
            nxt[1] = *reinterpret_cast<const float2*>(pB + k + c2);
            nxt[2] = *reinterpret_cast<const float2*>(pA + k + 8 + c2);
            nxt[3] = *reinterpret_cast<const float2*>(pB + k + 8 + c2);
        }

        unsigned ahi[4], alo[4];
        split2(cur[0], ahi[0], alo[0]);
        split2(cur[1], ahi[1], alo[1]);
        split2(cur[2], ahi[2], alo[2]);
        split2(cur[3], ahi[3], alo[3]);

        const uint4* __restrict__ wp = wbase + s * 4;
        #pragma unroll
        for (int nt = 0; nt < 27; nt++) {
            uint4 bw = __ldg(wp + (size_t)nt * (8 * NS * 4));
            unsigned bhi[2] = { bw.x, bw.y };
            unsigned blo[2] = { bw.z, bw.w };
            mma16816(acc[nt], ahi, bhi);
            mma16816(acc[nt], ahi, blo);
            mma16816(acc[nt], alo, bhi);
        }

        cur[0] = nxt[0]; cur[1] = nxt[1]; cur[2] = nxt[2]; cur[3] = nxt[3];
    }

    // Epilogue: K -> packed, Q -> packed (prescaled), V -> fp32
    const size_t rA = (size_t)(m0 + g);
    const size_t rB = (size_t)(m0 + g + 8);
    #pragma unroll
    for (int nt = 0; nt < 27; nt++) {
        const int which = nt / 9;
        const int nb    = nt - which * 9;
        if (which == 0) {
            const int pp = nb * 4 + c2g;
            g_Kp_hi[rA * HPAIR + pp] = pack_hi2(acc[nt][0], acc[nt][1]);
            g_Kp_lo[rA * HPAIR + pp] = pack_lo2(acc[nt][0], acc[nt][1]);
            g_Kp_hi[rB * HPAIR + pp] = pack_hi2(acc[nt][2], acc[nt][3]);
            g_Kp_lo[rB * HPAIR + pp] = pack_lo2(acc[nt][2], acc[nt][3]);
        } else if (which == 1) {
            const int pp = nb * 4 + c2g;
            float q0 = acc[nt][0] * QSCALE, q1 = acc[nt][1] * QSCALE;
            float q2 = acc[nt][2] * QSCALE, q3 = acc[nt][3] * QSCALE;
            g_Qp_hi[rA * HPAIR + pp] = pack_hi2(q0, q1);
            g_Qp_lo[rA * HPAIR + pp] = pack_lo2(q0, q1);
            g_Qp_hi[rB * HPAIR + pp] = pack_hi2(q2, q3);
            g_Qp_lo[rB * HPAIR + pp] = pack_lo2(q2, q3);
        } else {
            const int col = nb * 8 + c2;
            *reinterpret_cast<float2*>(&g_V[rA * H + col]) =
                make_float2(acc[nt][0], acc[nt][1]);
            *reinterpret_cast<float2*>(&g_V[rB * H + col]) =
                make_float2(acc[nt][2], acc[nt][3]);
        }
    }
}

// ---------------------------------------------------------------------------
// vpack: fp32 V -> hi/lo bf16x2 token-pairs, layout [b][n][256]
// ---------------------------------------------------------------------------
__global__ __launch_bounds__(256) void vpack_kernel()
{
    int idx = blockIdx.x * 256 + threadIdx.x;   // over B*H*TPAIR
    if (idx >= B * H * TPAIR) return;
    int p = idx & (TPAIR - 1);
    int n = (idx >> 8) % H;
    int b = idx / (H * TPAIR);
    float v0 = g_V[((size_t)b * T + 2 * p)     * H + n];
    float v1 = g_V[((size_t)b * T + 2 * p + 1) * H + n];
    g_Vp_hi[idx] = pack_hi2(v0, v1);
    g_Vp_lo[idx] = pack_lo2(v0, v1);
}

// ---------------------------------------------------------------------------
// Tensor-core flash attention. 128 threads (4 warps), BR=64 (16 rows/warp),
// BC=64. No smem; softmax state replicated in quad lanes.
// ---------------------------------------------------------------------------
__global__ __launch_bounds__(128) void attn_kernel(float* __restrict__ out)
{
    const int qt = (int)(gridDim.x - 1 - blockIdx.x);   // heavy tiles first
    const int b  = blockIdx.y;
    const int t  = threadIdx.x;
    const int w    = t >> 5;
    const int lane = t & 31;
    const int g    = lane >> 2;
    const int li   = lane & 3;

    const int row0 = qt * 64 + w * 16;          // row base within batch
    const size_t qbase = (size_t)b * T + row0;

    // ---- Q fragments: load once, keep in registers ----
    unsigned qhi[5][4], qlo[5][4];
    #pragma unroll
    for (int ks = 0; ks < 5; ks++) {
        if (ks < 4) {
            const int p0 = ks * 8 + li, p1 = ks * 8 + 4 + li;
            qhi[ks][0] = g_Qp_hi[(qbase + g)     * HPAIR + p0];
            qhi[ks][1] = g_Qp_hi[(qbase + g + 8) * HPAIR + p0];
            qhi[ks][2] = g_Qp_hi[(qbase + g)     * HPAIR + p1];
            qhi[ks][3] = g_Qp_hi[(qbase + g + 8) * HPAIR + p1];
            qlo[ks][0] = g_Qp_lo[(qbase + g)     * HPAIR + p0];
            qlo[ks][1] = g_Qp_lo[(qbase + g + 8) * HPAIR + p0];
            qlo[ks][2] = g_Qp_lo[(qbase + g)     * HPAIR + p1];
            qlo[ks][3] = g_Qp_lo[(qbase + g + 8) * HPAIR + p1];
        } else {
            const int p0 = 32 + li;
            qhi[4][0] = g_Qp_hi[(qbase + g)     * HPAIR + p0];
            qhi[4][1] = g_Qp_hi[(qbase + g + 8) * HPAIR + p0];
            qhi[4][2] = 0; qhi[4][3] = 0;
            qlo[4][0] = g_Qp_lo[(qbase + g)     * HPAIR + p0];
            qlo[4][1] = g_Qp_lo[(qbase + g + 8) * HPAIR + p0];
            qlo[4][2] = 0; qlo[4][3] = 0;
        }
    }

    float m0r = -1e30f, m1r = -1e30f, l0 = 0.f, l1 = 0.f;
    float o[9][4];
    #pragma unroll
    for (int j = 0; j < 9; j++)
        #pragma unroll
        for (int i = 0; i < 4; i++) o[j][i] = 0.f;

    for (int kt = 0; kt <= qt; kt++) {
        const size_t kbase = (size_t)b * T + kt * 64;

        // ---- S = Q K^T : 8 n8 blocks x 5 k-steps, 3-term split ----
        float s[8][4];
        #pragma unroll
        for (int nb = 0; nb < 8; nb++)
            #pragma unroll
            for (int i = 0; i < 4; i++) s[nb][i] = 0.f;

        #pragma unroll
        for (int ks = 0; ks < 5; ks++) {
            #pragma unroll
            for (int nb = 0; nb < 8; nb++) {
                const size_t rk = (kbase + nb * 8 + g) * HPAIR;
                unsigned bh[2], bl[2];
                if (ks < 4) {
                    bh[0] = g_Kp_hi[rk + ks * 8 + li];
                    bh[1] = g_Kp_hi[rk + ks * 8 + 4 + li];
                    bl[0] = g_Kp_lo[rk + ks * 8 + li];
                    bl[1] = g_Kp_lo[rk + ks * 8 + 4 + li];
                } else {
                    bh[0] = g_Kp_hi[rk + 32 + li]; bh[1] = 0;
                    bl[0] = g_Kp_lo[rk + 32 + li]; bl[1] = 0;
                }
                mma16816(s[nb], qhi[ks], bh);
                mma16816(s[nb], qhi[ks], bl);
                mma16816(s[nb], qlo[ks], bh);
            }
        }

        // ---- causal mask (diagonal tile only) ----
        if (kt == qt) {
            const int r0g = row0 + g, r1g = row0 + g + 8;
            #pragma unroll
            for (int nb = 0; nb < 8; nb++) {
                const int c = qt * 64 + nb * 8 + 2 * li;
                if (c     > r0g) s[nb][0] = -1e30f;
                if (c + 1 > r0g) s[nb][1] = -1e30f;
                if (c     > r1g) s[nb][2] = -1e30f;
                if (c + 1 > r1g) s[nb][3] = -1e30f;
            }
        }

        // ---- online softmax (quad-replicated state) ----
        float rm0 = -1e30f, rm1 = -1e30f;
        #pragma unroll
        for (int nb = 0; nb < 8; nb++) {
            rm0 = fmaxf(rm0, fmaxf(s[nb][0], s[nb][1]));
            rm1 = fmaxf(rm1, fmaxf(s[nb][2], s[nb][3]));
        }
        rm0 = fmaxf(rm0, __shfl_xor_sync(0xffffffffu, rm0, 1));
        rm0 = fmaxf(rm0, __shfl_xor_sync(0xffffffffu, rm0, 2));
        rm1 = fmaxf(rm1, __shfl_xor_sync(0xffffffffu, rm1, 1));
        rm1 = fmaxf(rm1, __shfl_xor_sync(0xffffffffu, rm1, 2));

        const float mn0 = fmaxf(m0r, rm0);
        const float mn1 = fmaxf(m1r, rm1);
        const float sc0 = __expf(m0r - mn0);
        const float sc1 = __expf(m1r - mn1);

        float rs0 = 0.f, rs1 = 0.f;
        #pragma unroll
        for (int nb = 0; nb < 8; nb++) {
            s[nb][0] = __expf(s[nb][0] - mn0);
            s[nb][1] = __expf(s[nb][1] - mn0);
            s[nb][2] = __expf(s[nb][2] - mn1);
            s[nb][3] = __expf(s[nb][3] - mn1);
            rs0 += s[nb][0] + s[nb][1];
            rs1 += s[nb][2] + s[nb][3];
        }
        rs0 += __shfl_xor_sync(0xffffffffu, rs0, 1);
        rs0 += __shfl_xor_sync(0xffffffffu, rs0, 2);
        rs1 += __shfl_xor_sync(0xffffffffu, rs1, 1);
        rs1 += __shfl_xor_sync(0xffffffffu, rs1, 2);

        l0 = l0 * sc0 + rs0;
        l1 = l1 * sc1 + rs1;
        m0r = mn0; m1r = mn1;

        #pragma unroll
        for (int j = 0; j < 9; j++) {
            o[j][0] *= sc0; o[j][1] *= sc0;
            o[j][2] *= sc1; o[j][3] *= sc1;
        }

        // ---- O += P V : P C-frag == A-frag, split hi/lo on the fly ----
        #pragma unroll
        for (int ks = 0; ks < 4; ks++) {
            unsigned ph[4], pl[4];
            ph[0] = pack_hi2(s[2*ks][0],   s[2*ks][1]);
            pl[0] = pack_lo2(s[2*ks][0],   s[2*ks][1]);
            ph[1] = pack_hi2(s[2*ks][2],   s[2*ks][3]);
            pl[1] = pack_lo2(s[2*ks][2],   s[2*ks][3]);
            ph[2] = pack_hi2(s[2*ks+1][0], s[2*ks+1][1]);
            pl[2] = pack_lo2(s[2*ks+1][0], s[2*ks+1][1]);
            ph[3] = pack_hi2(s[2*ks+1][2], s[2*ks+1][3]);
            pl[3] = pack_lo2(s[2*ks+1][2], s[2*ks+1][3]);

            #pragma unroll
            for (int nb = 0; nb < 9; nb++) {
                const size_t rv = ((size_t)b * H + nb * 8 + g) * TPAIR + kt * 32 + ks * 8;
                unsigned vh[2] = { g_Vp_hi[rv + li], g_Vp_hi[rv + 4 + li] };
                unsigned vl[2] = { g_Vp_lo[rv + li], g_Vp_lo[rv + 4 + li] };
                mma16816(o[nb], ph, vh);
                mma16816(o[nb], ph, vl);
                mma16816(o[nb], pl, vh);
            }
        }
    }

    // ---- epilogue ----
    const float inv0 = 1.f / l0;
    const float inv1 = 1.f / l1;
    float* od0 = out + (qbase + g)     * H;
    float* od1 = out + (qbase + g + 8) * H;
    #pragma unroll
    for (int nb = 0; nb < 9; nb++) {
        const int col = nb * 8 + 2 * li;
        *reinterpret_cast<float2*>(od0 + col) = make_float2(o[nb][0] * inv0, o[nb][1] * inv0);
        *reinterpret_cast<float2*>(od1 + col) = make_float2(o[nb][2] * inv1, o[nb][3] * inv1);
    }
}

// ---------------------------------------------------------------------------
extern "C" void kernel_launch(void* const* d_in, const int* in_sizes, int n_in,
                              void* d_out, int out_size)
{
    const float* x  = (const float*)d_in[0];
    const float* Wk = (const float*)d_in[1];
    const float* Wq = (const float*)d_in[2];
    const float* Wv = (const float*)d_in[3];
    float* out = (float*)d_out;

    prep_w<<<(WPIDX + 255) / 256, 256>>>(Wk, Wq, Wv);
    proj_kernel<<<BT / 128, 256>>>(x);
    vpack_kernel<<<(B * H * TPAIR + 255) / 256, 256>>>();
    attn_kernel<<<dim3(T / 64, B), 128>>>(out);
}

// round 6
// speedup vs baseline: 3.3477x; 1.4870x over previous
#include <cuda_runtime.h>
#include <cuda_bf16.h>
#include <math.h>

#define B 64
#define T 512
#define E 768
#define H 72
#define BT (B*T)

#define NS   48              // k16 steps over K=768
#define NG   216             // total output cols (3*72)
#define WPIDX (NG*NS*4)      // uint4 count in packed W
#define HPAIR 36             // h-pairs per row for packed Q/K
#define TPAIR 256            // token-pairs per batch for packed V

#define QSCALE 0.11785113019775793f   // 1/sqrt(72)

// Scratch (static device globals -- no allocation in kernel_launch)
__device__ float g_V[BT*H];
__device__ unsigned g_Qp_hi[BT*HPAIR];
__device__ unsigned g_Qp_lo[BT*HPAIR];
__device__ unsigned g_Kp_hi[BT*HPAIR];
__device__ unsigned g_Kp_lo[BT*HPAIR];
// V packed transposed: [b][pair p][n]  (p = token pair 0..255, n = 0..71)
__device__ unsigned g_Vp_hi[B*TPAIR*H];
__device__ unsigned g_Vp_lo[B*TPAIR*H];
__device__ uint4 g_Wp[WPIDX];

__device__ __forceinline__ void mma16816(float* c, const unsigned* a, const unsigned* b)
{
    asm volatile(
        "mma.sync.aligned.m16n8k16.row.col.f32.bf16.bf16.f32 "
        "{%0,%1,%2,%3}, {%4,%5,%6,%7}, {%8,%9}, {%0,%1,%2,%3};\n"
        : "+f"(c[0]), "+f"(c[1]), "+f"(c[2]), "+f"(c[3])
        : "r"(a[0]), "r"(a[1]), "r"(a[2]), "r"(a[3]), "r"(b[0]), "r"(b[1]));
}

__device__ __forceinline__ unsigned pack_hi2(float a, float b)
{
    __nv_bfloat162 p = __halves2bfloat162(__float2bfloat16(a), __float2bfloat16(b));
    return *reinterpret_cast<unsigned*>(&p);
}
__device__ __forceinline__ unsigned pack_lo2(float a, float b)
{
    __nv_bfloat16 ha = __float2bfloat16(a);
    __nv_bfloat16 hb = __float2bfloat16(b);
    __nv_bfloat162 p = __halves2bfloat162(
        __float2bfloat16(a - __bfloat162float(ha)),
        __float2bfloat16(b - __bfloat162float(hb)));
    return *reinterpret_cast<unsigned*>(&p);
}
__device__ __forceinline__ void split2(float2 v, unsigned& hi, unsigned& lo)
{
    hi = pack_hi2(v.x, v.y);
    lo = pack_lo2(v.x, v.y);
}

__device__ __forceinline__ void cp16(unsigned smaddr, const void* gptr)
{
    asm volatile("cp.async.cg.shared.global [%0], [%1], 16;\n"
                 :: "r"(smaddr), "l"(gptr));
}

// ---------------------------------------------------------------------------
// prep_w: pack Wk|Wq|Wv into mma B-fragment layout (global, L2-resident)
// ---------------------------------------------------------------------------
__global__ __launch_bounds__(256) void prep_w(
    const float* __restrict__ Wk,
    const float* __restrict__ Wq,
    const float* __restrict__ Wv)
{
    int idx = blockIdx.x * 256 + threadIdx.x;
    if (idx >= WPIDX) return;
    int c2g = idx & 3;
    int s   = (idx >> 2) % NS;
    int ng  = idx / (4 * NS);
    int which = ng / H;
    int n     = ng - which * H;
    const float* __restrict__ W = (which == 0) ? Wk : ((which == 1) ? Wq : Wv);
    int k = s * 16 + c2g * 2;
    float w00 = W[(size_t)(k + 0) * H + n];
    float w01 = W[(size_t)(k + 1) * H + n];
    float w10 = W[(size_t)(k + 8) * H + n];
    float w11 = W[(size_t)(k + 9) * H + n];
    uint4 p;
    p.x = pack_hi2(w00, w01);
    p.y = pack_hi2(w10, w11);
    p.z = pack_lo2(w00, w01);
    p.w = pack_lo2(w10, w11);
    g_Wp[idx] = p;
}

// ---------------------------------------------------------------------------
// Fused projection GEMM (K,Q,V): emits K,Q packed hi/lo bf16x2 h-pairs
// (Q pre-scaled by 1/sqrt(H)), V as fp32.
// ---------------------------------------------------------------------------
__global__ __launch_bounds__(256) void proj_kernel(const float* __restrict__ x)
{
    const int t    = threadIdx.x;
    const int wid  = t >> 5;
    const int lane = t & 31;
    const int g    = lane >> 2;
    const int c2   = (lane & 3) * 2;
    const int c2g  = lane & 3;

    const int m0 = blockIdx.x * 128 + wid * 16;
    const float* __restrict__ pA = x + (size_t)(m0 + g) * E;
    const float* __restrict__ pB = x + (size_t)(m0 + g + 8) * E;

    float acc[27][4];
    #pragma unroll
    for (int nt = 0; nt < 27; nt++)
        #pragma unroll
        for (int i = 0; i < 4; i++) acc[nt][i] = 0.f;

    const uint4* __restrict__ wbase = g_Wp + (size_t)(g * NS) * 4 + c2g;

    float2 cur[4];
    cur[0] = *reinterpret_cast<const float2*>(pA + c2);
    cur[1] = *reinterpret_cast<const float2*>(pB + c2);
    cur[2] = *reinterpret_cast<const float2*>(pA + 8 + c2);
    cur[3] = *reinterpret_cast<const float2*>(pB + 8 + c2);

    for (int s = 0; s < NS; s++) {
        float2 nxt[4];
        if (s < NS - 1) {
            const int k = (s + 1) * 16;
            nxt[0] = *reinterpret_cast<const float2*>(pA + k + c2);
            nxt[1] = *reinterpret_cast<const float2*>(pB + k + c2);
            nxt[2] = *reinterpret_cast<const float2*>(pA + k + 8 + c2);
            nxt[3] = *reinterpret_cast<const float2*>(pB + k + 8 + c2);
        }

        unsigned ahi[4], alo[4];
        split2(cur[0], ahi[0], alo[0]);
        split2(cur[1], ahi[1], alo[1]);
        split2(cur[2], ahi[2], alo[2]);
        split2(cur[3], ahi[3], alo[3]);

        const uint4* __restrict__ wp = wbase + s * 4;
        #pragma unroll
        for (int nt = 0; nt < 27; nt++) {
            uint4 bw = __ldg(wp + (size_t)nt * (8 * NS * 4));
            unsigned bhi[2] = { bw.x, bw.y };
            unsigned blo[2] = { bw.z, bw.w };
            mma16816(acc[nt], ahi, bhi);
            mma16816(acc[nt], ahi, blo);
            mma16816(acc[nt], alo, bhi);
        }

        cur[0] = nxt[0]; cur[1] = nxt[1]; cur[2] = nxt[2]; cur[3] = nxt[3];
    }

    // Epilogue: K -> packed, Q -> packed (prescaled), V -> fp32
    const size_t rA = (size_t)(m0 + g);
    const size_t rB = (size_t)(m0 + g + 8);
    #pragma unroll
    for (int nt = 0; nt < 27; nt++) {
        const int which = nt / 9;
        const int nb    = nt - which * 9;
        if (which == 0) {
            const int pp = nb * 4 + c2g;
            g_Kp_hi[rA * HPAIR + pp] = pack_hi2(acc[nt][0], acc[nt][1]);
            g_Kp_lo[rA * HPAIR + pp] = pack_lo2(acc[nt][0], acc[nt][1]);
            g_Kp_hi[rB * HPAIR + pp] = pack_hi2(acc[nt][2], acc[nt][3]);
            g_Kp_lo[rB * HPAIR + pp] = pack_lo2(acc[nt][2], acc[nt][3]);
        } else if (which == 1) {
            const int pp = nb * 4 + c2g;
            float q0 = acc[nt][0] * QSCALE, q1 = acc[nt][1] * QSCALE;
            float q2 = acc[nt][2] * QSCALE, q3 = acc[nt][3] * QSCALE;
            g_Qp_hi[rA * HPAIR + pp] = pack_hi2(q0, q1);
            g_Qp_lo[rA * HPAIR + pp] = pack_lo2(q0, q1);
            g_Qp_hi[rB * HPAIR + pp] = pack_hi2(q2, q3);
            g_Qp_lo[rB * HPAIR + pp] = pack_lo2(q2, q3);
        } else {
            const int col = nb * 8 + c2;
            *reinterpret_cast<float2*>(&g_V[rA * H + col]) =
                make_float2(acc[nt][0], acc[nt][1]);
            *reinterpret_cast<float2*>(&g_V[rB * H + col]) =
                make_float2(acc[nt][2], acc[nt][3]);
        }
    }
}

// ---------------------------------------------------------------------------
// vpack: fp32 V -> hi/lo bf16x2 token-pairs, TRANSPOSED layout [b][p][n]
// ---------------------------------------------------------------------------
__global__ __launch_bounds__(256) void vpack_kernel()
{
    int idx = blockIdx.x * 256 + threadIdx.x;   // over B*TPAIR*H, n fastest
    if (idx >= B * TPAIR * H) return;
    int n   = idx % H;
    int rem = idx / H;
    int p   = rem % TPAIR;
    int b   = rem / TPAIR;
    float v0 = g_V[((size_t)b * T + 2 * p)     * H + n];
    float v1 = g_V[((size_t)b * T + 2 * p + 1) * H + n];
    g_Vp_hi[idx] = pack_hi2(v0, v1);
    g_Vp_lo[idx] = pack_lo2(v0, v1);
}

// ---------------------------------------------------------------------------
// Tensor-core flash attention, smem-staged with cp.async double buffering.
// 128 threads (4 warps), BR=64 (16 rows/warp), BC=64.
// Stage (u32 units): Kh[64*36] Kl[64*36] Vh[32*72] Vl[32*72] = 9216 u32 = 36KB
// ---------------------------------------------------------------------------
#define STG_U32 9216
#define KOFF_L  2304
#define VOFF_H  4608
#define VOFF_L  6912

__global__ __launch_bounds__(128) void attn_kernel(float* __restrict__ out)
{
    extern __shared__ unsigned smn[];
    const unsigned smbase = (unsigned)__cvta_generic_to_shared(smn);

    const int qt = (int)(gridDim.x - 1 - blockIdx.x);   // heavy tiles first
    const int b  = blockIdx.y;
    const int t  = threadIdx.x;
    const int w    = t >> 5;
    const int lane = t & 31;
    const int g    = lane >> 2;
    const int li   = lane & 3;

    const int row0 = qt * 64 + w * 16;
    const size_t qbase = (size_t)b * T + row0;

    // ---- Q fragments: load once, keep in registers ----
    unsigned qhi[5][4], qlo[5][4];
    #pragma unroll
    for (int ks = 0; ks < 5; ks++) {
        if (ks < 4) {
            const int p0 = ks * 8 + li, p1 = ks * 8 + 4 + li;
            qhi[ks][0] = g_Qp_hi[(qbase + g)     * HPAIR + p0];
            qhi[ks][1] = g_Qp_hi[(qbase + g + 8) * HPAIR + p0];
            qhi[ks][2] = g_Qp_hi[(qbase + g)     * HPAIR + p1];
            qhi[ks][3] = g_Qp_hi[(qbase + g + 8) * HPAIR + p1];
            qlo[ks][0] = g_Qp_lo[(qbase + g)     * HPAIR + p0];
            qlo[ks][1] = g_Qp_lo[(qbase + g + 8) * HPAIR + p0];
            qlo[ks][2] = g_Qp_lo[(qbase + g)     * HPAIR + p1];
            qlo[ks][3] = g_Qp_lo[(qbase + g + 8) * HPAIR + p1];
        } else {
            const int p0 = 32 + li;
            qhi[4][0] = g_Qp_hi[(qbase + g)     * HPAIR + p0];
            qhi[4][1] = g_Qp_hi[(qbase + g + 8) * HPAIR + p0];
            qhi[4][2] = 0; qhi[4][3] = 0;
            qlo[4][0] = g_Qp_lo[(qbase + g)     * HPAIR + p0];
            qlo[4][1] = g_Qp_lo[(qbase + g + 8) * HPAIR + p0];
            qlo[4][2] = 0; qlo[4][3] = 0;
        }
    }

    // ---- tile fill via cp.async (4 contiguous 9216B blocks) ----
    auto fill = [&](int stage, int kt) {
        const unsigned dst = smbase + stage * (STG_U32 * 4);
        const char* sK_h = (const char*)(g_Kp_hi + ((size_t)b * T + kt * 64) * HPAIR);
        const char* sK_l = (const char*)(g_Kp_lo + ((size_t)b * T + kt * 64) * HPAIR);
        const char* sV_h = (const char*)(g_Vp_hi + ((size_t)b * TPAIR + kt * 32) * H);
        const char* sV_l = (const char*)(g_Vp_lo + ((size_t)b * TPAIR + kt * 32) * H);
        // each block: 9216B = 576 x 16B chunks
        for (int i = t; i < 576; i += 128) {
            const int o = i * 16;
            cp16(dst + o,                 sK_h + o);
            cp16(dst + KOFF_L * 4 + o,    sK_l + o);
            cp16(dst + VOFF_H * 4 + o,    sV_h + o);
            cp16(dst + VOFF_L * 4 + o,    sV_l + o);
        }
    };

    fill(0, 0);
    asm volatile("cp.async.commit_group;\n");

    float m0r = -1e30f, m1r = -1e30f, l0 = 0.f, l1 = 0.f;
    float o[9][4];
    #pragma unroll
    for (int j = 0; j < 9; j++)
        #pragma unroll
        for (int i = 0; i < 4; i++) o[j][i] = 0.f;

    for (int kt = 0; kt <= qt; kt++) {
        if (kt < qt) {
            fill((kt + 1) & 1, kt + 1);
            asm volatile("cp.async.commit_group;\n");
            asm volatile("cp.async.wait_group 1;\n");
        } else {
            asm volatile("cp.async.wait_group 0;\n");
        }
        __syncthreads();

        const unsigned* __restrict__ st = smn + (kt & 1) * STG_U32;
        const unsigned* __restrict__ Kh = st;
        const unsigned* __restrict__ Kl = st + KOFF_L;
        const unsigned* __restrict__ Vh = st + VOFF_H;
        const unsigned* __restrict__ Vl = st + VOFF_L;

        // ---- S = Q K^T ----
        float s[8][4];
        #pragma unroll
        for (int nb = 0; nb < 8; nb++)
            #pragma unroll
            for (int i = 0; i < 4; i++) s[nb][i] = 0.f;

        #pragma unroll
        for (int ks = 0; ks < 5; ks++) {
            #pragma unroll
            for (int nb = 0; nb < 8; nb++) {
                const int rk = (nb * 8 + g) * HPAIR;
                unsigned bh[2], bl[2];
                if (ks < 4) {
                    bh[0] = Kh[rk + ks * 8 + li];
                    bh[1] = Kh[rk + ks * 8 + 4 + li];
                    bl[0] = Kl[rk + ks * 8 + li];
                    bl[1] = Kl[rk + ks * 8 + 4 + li];
                } else {
                    bh[0] = Kh[rk + 32 + li]; bh[1] = 0;
                    bl[0] = Kl[rk + 32 + li]; bl[1] = 0;
                }
                mma16816(s[nb], qhi[ks], bh);
                mma16816(s[nb], qhi[ks], bl);
                mma16816(s[nb], qlo[ks], bh);
            }
        }

        // ---- causal mask (diagonal tile only) ----
        if (kt == qt) {
            const int r0g = row0 + g, r1g = row0 + g + 8;
            #pragma unroll
            for (int nb = 0; nb < 8; nb++) {
                const int c = qt * 64 + nb * 8 + 2 * li;
                if (c     > r0g) s[nb][0] = -1e30f;
                if (c + 1 > r0g) s[nb][1] = -1e30f;
                if (c     > r1g) s[nb][2] = -1e30f;
                if (c + 1 > r1g) s[nb][3] = -1e30f;
            }
        }

        // ---- online softmax (quad-replicated state) ----
        float rm0 = -1e30f, rm1 = -1e30f;
        #pragma unroll
        for (int nb = 0; nb < 8; nb++) {
            rm0 = fmaxf(rm0, fmaxf(s[nb][0], s[nb][1]));
            rm1 = fmaxf(rm1, fmaxf(s[nb][2], s[nb][3]));
        }
        rm0 = fmaxf(rm0, __shfl_xor_sync(0xffffffffu, rm0, 1));
        rm0 = fmaxf(rm0, __shfl_xor_sync(0xffffffffu, rm0, 2));
        rm1 = fmaxf(rm1, __shfl_xor_sync(0xffffffffu, rm1, 1));
        rm1 = fmaxf(rm1, __shfl_xor_sync(0xffffffffu, rm1, 2));

        const float mn0 = fmaxf(m0r, rm0);
        const float mn1 = fmaxf(m1r, rm1);
        const float sc0 = __expf(m0r - mn0);
        const float sc1 = __expf(m1r - mn1);

        float rs0 = 0.f, rs1 = 0.f;
        #pragma unroll
        for (int nb = 0; nb < 8; nb++) {
            s[nb][0] = __expf(s[nb][0] - mn0);
            s[nb][1] = __expf(s[nb][1] - mn0);
            s[nb][2] = __expf(s[nb][2] - mn1);
            s[nb][3] = __expf(s[nb][3] - mn1);
            rs0 += s[nb][0] + s[nb][1];
            rs1 += s[nb][2] + s[nb][3];
        }
        rs0 += __shfl_xor_sync(0xffffffffu, rs0, 1);
        rs0 += __shfl_xor_sync(0xffffffffu, rs0, 2);
        rs1 += __shfl_xor_sync(0xffffffffu, rs1, 1);
        rs1 += __shfl_xor_sync(0xffffffffu, rs1, 2);

        l0 = l0 * sc0 + rs0;
        l1 = l1 * sc1 + rs1;
        m0r = mn0; m1r = mn1;

        #pragma unroll
        for (int j = 0; j < 9; j++) {
            o[j][0] *= sc0; o[j][1] *= sc0;
            o[j][2] *= sc1; o[j][3] *= sc1;
        }

        // ---- O += P V : V transposed in smem [p][n], bank-conflict-free ----
        #pragma unroll
        for (int ks = 0; ks < 4; ks++) {
            unsigned ph[4], pl[4];
            ph[0] = pack_hi2(s[2*ks][0],   s[2*ks][1]);
            pl[0] = pack_lo2(s[2*ks][0],   s[2*ks][1]);
            ph[1] = pack_hi2(s[2*ks][2],   s[2*ks][3]);
            pl[1] = pack_lo2(s[2*ks][2],   s[2*ks][3]);
            ph[2] = pack_hi2(s[2*ks+1][0], s[2*ks+1][1]);
            pl[2] = pack_lo2(s[2*ks+1][0], s[2*ks+1][1]);
            ph[3] = pack_hi2(s[2*ks+1][2], s[2*ks+1][3]);
            pl[3] = pack_lo2(s[2*ks+1][2], s[2*ks+1][3]);

            const int rv0 = (ks * 8 + li) * H;
            const int rv1 = (ks * 8 + 4 + li) * H;
            #pragma unroll
            for (int nb = 0; nb < 9; nb++) {
                const int cn = nb * 8 + g;
                unsigned vh[2] = { Vh[rv0 + cn], Vh[rv1 + cn] };
                unsigned vl[2] = { Vl[rv0 + cn], Vl[rv1 + cn] };
                mma16816(o[nb], ph, vh);
                mma16816(o[nb], ph, vl);
                mma16816(o[nb], pl, vh);
            }
        }
        __syncthreads();   // all warps done with this stage before refill
    }

    // ---- epilogue ----
    const float inv0 = 1.f / l0;
    const float inv1 = 1.f / l1;
    float* od0 = out + (qbase + g)     * H;
    float* od1 = out + (qbase + g + 8) * H;
    #pragma unroll
    for (int nb = 0; nb < 9; nb++) {
        const int col = nb * 8 + 2 * li;
        *reinterpret_cast<float2*>(od0 + col) = make_float2(o[nb][0] * inv0, o[nb][1] * inv0);
        *reinterpret_cast<float2*>(od1 + col) = make_float2(o[nb][2] * inv1, o[nb][3] * inv1);
    }
}

// ---------------------------------------------------------------------------
extern "C" void kernel_launch(void* const* d_in, const int* in_sizes, int n_in,
                              void* d_out, int out_size)
{
    const float* x  = (const float*)d_in[0];
    const float* Wk = (const float*)d_in[1];
    const float* Wq = (const float*)d_in[2];
    const float* Wv = (const float*)d_in[3];
    float* out = (float*)d_out;

    prep_w<<<(WPIDX + 255) / 256, 256>>>(Wk, Wq, Wv);
    proj_kernel<<<BT / 128, 256>>>(x);
    vpack_kernel<<<(B * TPAIR * H + 255) / 256, 256>>>();

    const int smem = 2 * STG_U32 * 4 * (int)sizeof(unsigned) / 4;  // 73728 B
    cudaFuncSetAttribute(attn_kernel, cudaFuncAttributeMaxDynamicSharedMemorySize, 73728);
    attn_kernel<<<dim3(T / 64, B), 128, 73728>>>(out);
    (void)smem;
}

// round 7
// speedup vs baseline: 3.4075x; 1.0179x over previous
#include <cuda_runtime.h>
#include <cuda_bf16.h>
#include <math.h>

#define B 64
#define T 512
#define E 768
#define H 72
#define BT (B*T)

#define NS   48              // k16 steps over K=768
#define NG   216             // total output cols (3*72)
#define WPIDX (NG*NS*4)      // uint4 count in packed W
#define HPAIR 36             // h-pairs per row for packed Q/K
#define TPAIR 256            // token-pairs per batch for packed V

#define QSCALE 0.11785113019775793f   // 1/sqrt(72)

// Scratch (static device globals -- no allocation in kernel_launch)
__device__ float g_V[BT*H];
__device__ unsigned g_Qp_hi[BT*HPAIR];
__device__ unsigned g_Qp_lo[BT*HPAIR];
__device__ unsigned g_Kp_hi[BT*HPAIR];
__device__ unsigned g_Kp_lo[BT*HPAIR];
// V packed transposed: [b][pair p][n]  (p = token pair 0..255, n = 0..71)
__device__ unsigned g_Vp_hi[B*TPAIR*H];
__device__ unsigned g_Vp_lo[B*TPAIR*H];
__device__ uint4 g_Wp[WPIDX];

__device__ __forceinline__ void mma16816(float* c, const unsigned* a, const unsigned* b)
{
    asm volatile(
        "mma.sync.aligned.m16n8k16.row.col.f32.bf16.bf16.f32 "
        "{%0,%1,%2,%3}, {%4,%5,%6,%7}, {%8,%9}, {%0,%1,%2,%3};\n"
        : "+f"(c[0]), "+f"(c[1]), "+f"(c[2]), "+f"(c[3])
        : "r"(a[0]), "r"(a[1]), "r"(a[2]), "r"(a[3]), "r"(b[0]), "r"(b[1]));
}

__device__ __forceinline__ unsigned pack_hi2(float a, float b)
{
    __nv_bfloat162 p = __halves2bfloat162(__float2bfloat16(a), __float2bfloat16(b));
    return *reinterpret_cast<unsigned*>(&p);
}
__device__ __forceinline__ unsigned pack_lo2(float a, float b)
{
    __nv_bfloat16 ha = __float2bfloat16(a);
    __nv_bfloat16 hb = __float2bfloat16(b);
    __nv_bfloat162 p = __halves2bfloat162(
        __float2bfloat16(a - __bfloat162float(ha)),
        __float2bfloat16(b - __bfloat162float(hb)));
    return *reinterpret_cast<unsigned*>(&p);
}
__device__ __forceinline__ void split2(float2 v, unsigned& hi, unsigned& lo)
{
    hi = pack_hi2(v.x, v.y);
    lo = pack_lo2(v.x, v.y);
}

__device__ __forceinline__ void cp16(unsigned smaddr, const void* gptr)
{
    asm volatile("cp.async.cg.shared.global [%0], [%1], 16;\n"
                 :: "r"(smaddr), "l"(gptr));
}

// ---------------------------------------------------------------------------
// prep_w: pack Wk|Wq|Wv into mma B-fragment layout (global, L2-resident)
// ---------------------------------------------------------------------------
__global__ __launch_bounds__(256) void prep_w(
    const float* __restrict__ Wk,
    const float* __restrict__ Wq,
    const float* __restrict__ Wv)
{
    int idx = blockIdx.x * 256 + threadIdx.x;
    if (idx >= WPIDX) return;
    int c2g = idx & 3;
    int s   = (idx >> 2) % NS;
    int ng  = idx / (4 * NS);
    int which = ng / H;
    int n     = ng - which * H;
    const float* __restrict__ W = (which == 0) ? Wk : ((which == 1) ? Wq : Wv);
    int k = s * 16 + c2g * 2;
    float w00 = W[(size_t)(k + 0) * H + n];
    float w01 = W[(size_t)(k + 1) * H + n];
    float w10 = W[(size_t)(k + 8) * H + n];
    float w11 = W[(size_t)(k + 9) * H + n];
    uint4 p;
    p.x = pack_hi2(w00, w01);
    p.y = pack_hi2(w10, w11);
    p.z = pack_lo2(w00, w01);
    p.w = pack_lo2(w10, w11);
    g_Wp[idx] = p;
}

// ---------------------------------------------------------------------------
// Fused projection GEMM (K,Q,V), occupancy-optimized:
// CTA = 64 rows, 8 warps. Warps 0-3: rows (w&3)*16, nt 0..13.
//                        Warps 4-7: same rows,      nt 13..26.
// (nt=13 computed twice, identical values, benign double write.)
// acc[14][4] -> <=128 regs -> 2 CTAs/SM.
// ---------------------------------------------------------------------------
__global__ __launch_bounds__(256, 2) void proj_kernel(const float* __restrict__ x)
{
    const int t    = threadIdx.x;
    const int wid  = t >> 5;
    const int lane = t & 31;
    const int g    = lane >> 2;
    const int c2   = (lane & 3) * 2;
    const int c2g  = lane & 3;

    const int ntbase = (wid >> 2) * 13;          // 0 or 13
    const int m0 = blockIdx.x * 64 + (wid & 3) * 16;
    const float* __restrict__ pA = x + (size_t)(m0 + g) * E;
    const float* __restrict__ pB = x + (size_t)(m0 + g + 8) * E;

    float acc[14][4];
    #pragma unroll
    for (int j = 0; j < 14; j++)
        #pragma unroll
        for (int i = 0; i < 4; i++) acc[j][i] = 0.f;

    // B-frag base pointer for this lane/group (stride per nt = 8*48*4 uint4)
    const uint4* __restrict__ wbase =
        g_Wp + (size_t)(g * NS) * 4 + c2g + (size_t)ntbase * (8 * NS * 4);

    float2 cur[4];
    cur[0] = *reinterpret_cast<const float2*>(pA + c2);
    cur[1] = *reinterpret_cast<const float2*>(pB + c2);
    cur[2] = *reinterpret_cast<const float2*>(pA + 8 + c2);
    cur[3] = *reinterpret_cast<const float2*>(pB + 8 + c2);

    for (int s = 0; s < NS; s++) {
        float2 nxt[4];
        if (s < NS - 1) {
            const int k = (s + 1) * 16;
            nxt[0] = *reinterpret_cast<const float2*>(pA + k + c2);
            nxt[1] = *reinterpret_cast<const float2*>(pB + k + c2);
            nxt[2] = *reinterpret_cast<const float2*>(pA + k + 8 + c2);
            nxt[3] = *reinterpret_cast<const float2*>(pB + k + 8 + c2);
        }

        unsigned ahi[4], alo[4];
        split2(cur[0], ahi[0], alo[0]);
        split2(cur[1], ahi[1], alo[1]);
        split2(cur[2], ahi[2], alo[2]);
        split2(cur[3], ahi[3], alo[3]);

        const uint4* __restrict__ wp = wbase + s * 4;
        #pragma unroll
        for (int j = 0; j < 14; j++) {
            uint4 bw = __ldg(wp + (size_t)j * (8 * NS * 4));
            unsigned bhi[2] = { bw.x, bw.y };
            unsigned blo[2] = { bw.z, bw.w };
            mma16816(acc[j], ahi, bhi);
            mma16816(acc[j], ahi, blo);
            mma16816(acc[j], alo, bhi);
        }

        cur[0] = nxt[0]; cur[1] = nxt[1]; cur[2] = nxt[2]; cur[3] = nxt[3];
    }

    // Epilogue: nt_global = ntbase + j. K: 0..8, Q: 9..17 (prescaled), V: 18..26
    const size_t rA = (size_t)(m0 + g);
    const size_t rB = (size_t)(m0 + g + 8);
    #pragma unroll
    for (int j = 0; j < 14; j++) {
        const int ntg   = ntbase + j;
        const int which = ntg / 9;
        const int nb    = ntg - which * 9;
        if (which == 0) {
            const int pp = nb * 4 + c2g;
            g_Kp_hi[rA * HPAIR + pp] = pack_hi2(acc[j][0], acc[j][1]);
            g_Kp_lo[rA * HPAIR + pp] = pack_lo2(acc[j][0], acc[j][1]);
            g_Kp_hi[rB * HPAIR + pp] = pack_hi2(acc[j][2], acc[j][3]);
            g_Kp_lo[rB * HPAIR + pp] = pack_lo2(acc[j][2], acc[j][3]);
        } else if (which == 1) {
            const int pp = nb * 4 + c2g;
            float q0 = acc[j][0] * QSCALE, q1 = acc[j][1] * QSCALE;
            float q2 = acc[j][2] * QSCALE, q3 = acc[j][3] * QSCALE;
            g_Qp_hi[rA * HPAIR + pp] = pack_hi2(q0, q1);
            g_Qp_lo[rA * HPAIR + pp] = pack_lo2(q0, q1);
            g_Qp_hi[rB * HPAIR + pp] = pack_hi2(q2, q3);
            g_Qp_lo[rB * HPAIR + pp] = pack_lo2(q2, q3);
        } else {
            const int col = nb * 8 + c2;
            *reinterpret_cast<float2*>(&g_V[rA * H + col]) =
                make_float2(acc[j][0], acc[j][1]);
            *reinterpret_cast<float2*>(&g_V[rB * H + col]) =
                make_float2(acc[j][2], acc[j][3]);
        }
    }
}

// ---------------------------------------------------------------------------
// vpack: fp32 V -> hi/lo bf16x2 token-pairs, TRANSPOSED layout [b][p][n]
// ---------------------------------------------------------------------------
__global__ __launch_bounds__(256) void vpack_kernel()
{
    int idx = blockIdx.x * 256 + threadIdx.x;   // over B*TPAIR*H, n fastest
    if (idx >= B * TPAIR * H) return;
    int n   = idx % H;
    int rem = idx / H;
    int p   = rem % TPAIR;
    int b   = rem / TPAIR;
    float v0 = g_V[((size_t)b * T + 2 * p)     * H + n];
    float v1 = g_V[((size_t)b * T + 2 * p + 1) * H + n];
    g_Vp_hi[idx] = pack_hi2(v0, v1);
    g_Vp_lo[idx] = pack_lo2(v0, v1);
}

// ---------------------------------------------------------------------------
// Tensor-core flash attention, smem-staged with cp.async double buffering.
// 128 threads (4 warps), BR=64 (16 rows/warp), BC=64.
// Stage (u32 units): Kh[64*36] Kl[64*36] Vh[32*72] Vl[32*72] = 9216 u32 = 36KB
// ---------------------------------------------------------------------------
#define STG_U32 9216
#define KOFF_L  2304
#define VOFF_H  4608
#define VOFF_L  6912

__global__ __launch_bounds__(128) void attn_kernel(float* __restrict__ out)
{
    extern __shared__ unsigned smn[];
    const unsigned smbase = (unsigned)__cvta_generic_to_shared(smn);

    const int qt = (int)(gridDim.x - 1 - blockIdx.x);   // heavy tiles first
    const int b  = blockIdx.y;
    const int t  = threadIdx.x;
    const int w    = t >> 5;
    const int lane = t & 31;
    const int g    = lane >> 2;
    const int li   = lane & 3;

    const int row0 = qt * 64 + w * 16;
    const size_t qbase = (size_t)b * T + row0;

    // ---- Q fragments: load once, keep in registers ----
    unsigned qhi[5][4], qlo[5][4];
    #pragma unroll
    for (int ks = 0; ks < 5; ks++) {
        if (ks < 4) {
            const int p0 = ks * 8 + li, p1 = ks * 8 + 4 + li;
            qhi[ks][0] = g_Qp_hi[(qbase + g)     * HPAIR + p0];
            qhi[ks][1] = g_Qp_hi[(qbase + g + 8) * HPAIR + p0];
            qhi[ks][2] = g_Qp_hi[(qbase + g)     * HPAIR + p1];
            qhi[ks][3] = g_Qp_hi[(qbase + g + 8) * HPAIR + p1];
            qlo[ks][0] = g_Qp_lo[(qbase + g)     * HPAIR + p0];
            qlo[ks][1] = g_Qp_lo[(qbase + g + 8) * HPAIR + p0];
            qlo[ks][2] = g_Qp_lo[(qbase + g)     * HPAIR + p1];
            qlo[ks][3] = g_Qp_lo[(qbase + g + 8) * HPAIR + p1];
        } else {
            const int p0 = 32 + li;
            qhi[4][0] = g_Qp_hi[(qbase + g)     * HPAIR + p0];
            qhi[4][1] = g_Qp_hi[(qbase + g + 8) * HPAIR + p0];
            qhi[4][2] = 0; qhi[4][3] = 0;
            qlo[4][0] = g_Qp_lo[(qbase + g)     * HPAIR + p0];
            qlo[4][1] = g_Qp_lo[(qbase + g + 8) * HPAIR + p0];
            qlo[4][2] = 0; qlo[4][3] = 0;
        }
    }

    // ---- tile fill via cp.async (4 contiguous 9216B blocks) ----
    auto fill = [&](int stage, int kt) {
        const unsigned dst = smbase + stage * (STG_U32 * 4);
        const char* sK_h = (const char*)(g_Kp_hi + ((size_t)b * T + kt * 64) * HPAIR);
        const char* sK_l = (const char*)(g_Kp_lo + ((size_t)b * T + kt * 64) * HPAIR);
        const char* sV_h = (const char*)(g_Vp_hi + ((size_t)b * TPAIR + kt * 32) * H);
        const char* sV_l = (const char*)(g_Vp_lo + ((size_t)b * TPAIR + kt * 32) * H);
        for (int i = t; i < 576; i += 128) {
            const int o = i * 16;
            cp16(dst + o,                 sK_h + o);
            cp16(dst + KOFF_L * 4 + o,    sK_l + o);
            cp16(dst + VOFF_H * 4 + o,    sV_h + o);
            cp16(dst + VOFF_L * 4 + o,    sV_l + o);
        }
    };

    fill(0, 0);
    asm volatile("cp.async.commit_group;\n");

    float m0r = -1e30f, m1r = -1e30f, l0 = 0.f, l1 = 0.f;
    float o[9][4];
    #pragma unroll
    for (int j = 0; j < 9; j++)
        #pragma unroll
        for (int i = 0; i < 4; i++) o[j][i] = 0.f;

    for (int kt = 0; kt <= qt; kt++) {
        if (kt < qt) {
            fill((kt + 1) & 1, kt + 1);
            asm volatile("cp.async.commit_group;\n");
            asm volatile("cp.async.wait_group 1;\n");
        } else {
            asm volatile("cp.async.wait_group 0;\n");
        }
        __syncthreads();

        const unsigned* __restrict__ st = smn + (kt & 1) * STG_U32;
        const unsigned* __restrict__ Kh = st;
        const unsigned* __restrict__ Kl = st + KOFF_L;
        const unsigned* __restrict__ Vh = st + VOFF_H;
        const unsigned* __restrict__ Vl = st + VOFF_L;

        // ---- S = Q K^T ----
        float s[8][4];
        #pragma unroll
        for (int nb = 0; nb < 8; nb++)
            #pragma unroll
            for (int i = 0; i < 4; i++) s[nb][i] = 0.f;

        #pragma unroll
        for (int ks = 0; ks < 5; ks++) {
            #pragma unroll
            for (int nb = 0; nb < 8; nb++) {
                const int rk = (nb * 8 + g) * HPAIR;
                unsigned bh[2], bl[2];
                if (ks < 4) {
                    bh[0] = Kh[rk + ks * 8 + li];
                    bh[1] = Kh[rk + ks * 8 + 4 + li];
                    bl[0] = Kl[rk + ks * 8 + li];
                    bl[1] = Kl[rk + ks * 8 + 4 + li];
                } else {
                    bh[0] = Kh[rk + 32 + li]; bh[1] = 0;
                    bl[0] = Kl[rk + 32 + li]; bl[1] = 0;
                }
                mma16816(s[nb], qhi[ks], bh);
                mma16816(s[nb], qhi[ks], bl);
                mma16816(s[nb], qlo[ks], bh);
            }
        }

        // ---- causal mask (diagonal tile only) ----
        if (kt == qt) {
            const int r0g = row0 + g, r1g = row0 + g + 8;
            #pragma unroll
            for (int nb = 0; nb < 8; nb++) {
                const int c = qt * 64 + nb * 8 + 2 * li;
                if (c     > r0g) s[nb][0] = -1e30f;
                if (c + 1 > r0g) s[nb][1] = -1e30f;
                if (c     > r1g) s[nb][2] = -1e30f;
                if (c + 1 > r1g) s[nb][3] = -1e30f;
            }
        }

        // ---- online softmax (quad-replicated state) ----
        float rm0 = -1e30f, rm1 = -1e30f;
        #pragma unroll
        for (int nb = 0; nb < 8; nb++) {
            rm0 = fmaxf(rm0, fmaxf(s[nb][0], s[nb][1]));
            rm1 = fmaxf(rm1, fmaxf(s[nb][2], s[nb][3]));
        }
        rm0 = fmaxf(rm0, __shfl_xor_sync(0xffffffffu, rm0, 1));
        rm0 = fmaxf(rm0, __shfl_xor_sync(0xffffffffu, rm0, 2));
        rm1 = fmaxf(rm1, __shfl_xor_sync(0xffffffffu, rm1, 1));
        rm1 = fmaxf(rm1, __shfl_xor_sync(0xffffffffu, rm1, 2));

        const float mn0 = fmaxf(m0r, rm0);
        const float mn1 = fmaxf(m1r, rm1);
        const float sc0 = __expf(m0r - mn0);
        const float sc1 = __expf(m1r - mn1);

        float rs0 = 0.f, rs1 = 0.f;
        #pragma unroll
        for (int nb = 0; nb < 8; nb++) {
            s[nb][0] = __expf(s[nb][0] - mn0);
            s[nb][1] = __expf(s[nb][1] - mn0);
            s[nb][2] = __expf(s[nb][2] - mn1);
            s[nb][3] = __expf(s[nb][3] - mn1);
            rs0 += s[nb][0] + s[nb][1];
            rs1 += s[nb][2] + s[nb][3];
        }
        rs0 += __shfl_xor_sync(0xffffffffu, rs0, 1);
        rs0 += __shfl_xor_sync(0xffffffffu, rs0, 2);
        rs1 += __shfl_xor_sync(0xffffffffu, rs1, 1);
        rs1 += __shfl_xor_sync(0xffffffffu, rs1, 2);

        l0 = l0 * sc0 + rs0;
        l1 = l1 * sc1 + rs1;
        m0r = mn0; m1r = mn1;

        #pragma unroll
        for (int j = 0; j < 9; j++) {
            o[j][0] *= sc0; o[j][1] *= sc0;
            o[j][2] *= sc1; o[j][3] *= sc1;
        }

        // ---- O += P V : V transposed in smem [p][n], bank-conflict-free ----
        #pragma unroll
        for (int ks = 0; ks < 4; ks++) {
            unsigned ph[4], pl[4];
            ph[0] = pack_hi2(s[2*ks][0],   s[2*ks][1]);
            pl[0] = pack_lo2(s[2*ks][0],   s[2*ks][1]);
            ph[1] = pack_hi2(s[2*ks][2],   s[2*ks][3]);
            pl[1] = pack_lo2(s[2*ks][2],   s[2*ks][3]);
            ph[2] = pack_hi2(s[2*ks+1][0], s[2*ks+1][1]);
            pl[2] = pack_lo2(s[2*ks+1][0], s[2*ks+1][1]);
            ph[3] = pack_hi2(s[2*ks+1][2], s[2*ks+1][3]);
            pl[3] = pack_lo2(s[2*ks+1][2], s[2*ks+1][3]);

            const int rv0 = (ks * 8 + li) * H;
            const int rv1 = (ks * 8 + 4 + li) * H;
            #pragma unroll
            for (int nb = 0; nb < 9; nb++) {
                const int cn = nb * 8 + g;
                unsigned vh[2] = { Vh[rv0 + cn], Vh[rv1 + cn] };
                unsigned vl[2] = { Vl[rv0 + cn], Vl[rv1 + cn] };
                mma16816(o[nb], ph, vh);
                mma16816(o[nb], ph, vl);
                mma16816(o[nb], pl, vh);
            }
        }
        __syncthreads();   // all warps done with this stage before refill
    }

    // ---- epilogue ----
    const float inv0 = 1.f / l0;
    const float inv1 = 1.f / l1;
    float* od0 = out + (qbase + g)     * H;
    float* od1 = out + (qbase + g + 8) * H;
    #pragma unroll
    for (int nb = 0; nb < 9; nb++) {
        const int col = nb * 8 + 2 * li;
        *reinterpret_cast<float2*>(od0 + col) = make_float2(o[nb][0] * inv0, o[nb][1] * inv0);
        *reinterpret_cast<float2*>(od1 + col) = make_float2(o[nb][2] * inv1, o[nb][3] * inv1);
    }
}

// ---------------------------------------------------------------------------
extern "C" void kernel_launch(void* const* d_in, const int* in_sizes, int n_in,
                              void* d_out, int out_size)
{
    const float* x  = (const float*)d_in[0];
    const float* Wk = (const float*)d_in[1];
    const float* Wq = (const float*)d_in[2];
    const float* Wv = (const float*)d_in[3];
    float* out = (float*)d_out;

    prep_w<<<(WPIDX + 255) / 256, 256>>>(Wk, Wq, Wv);
    proj_kernel<<<BT / 64, 256>>>(x);
    vpack_kernel<<<(B * TPAIR * H + 255) / 256, 256>>>();

    cudaFuncSetAttribute(attn_kernel, cudaFuncAttributeMaxDynamicSharedMemorySize, 73728);
    attn_kernel<<<dim3(T / 64, B), 128, 73728>>>(out);
}